// round 2
// baseline (speedup 1.0000x reference)
#include <cuda_runtime.h>

#define NG   16
#define DD   64
#define TPB  256   // 1024 elems per row / 4 per thread

// 64 * log(2*pi)
#define D_LOG_2PI 117.6241322f

__global__ void __launch_bounds__(TPB) gmm_loss_kernel(
    const float* __restrict__ means,
    const float* __restrict__ covs,
    const float* __restrict__ weights,
    const float* __restrict__ targets,
    float* __restrict__ out)
{
    const int b   = blockIdx.x;
    const int tid = threadIdx.x;

    __shared__ float s_t[DD];
    __shared__ float s_lp[NG];

    // stage the target row (64 floats)
    if (tid < DD) s_t[tid] = targets[(size_t)b * DD + tid];
    __syncthreads();

    // Each thread handles 4 consecutive elements of the 1024-wide row.
    const int    base  = tid * 4;           // 0..1020
    const int    dbase = base & (DD - 1);   // position within the 64-dim vector
    const size_t row   = (size_t)b * (NG * DD);

    const float4 mu = *reinterpret_cast<const float4*>(means + row + base);
    const float4 vv = *reinterpret_cast<const float4*>(covs  + row + base);

    const float t0 = s_t[dbase + 0];
    const float t1 = s_t[dbase + 1];
    const float t2 = s_t[dbase + 2];
    const float t3 = s_t[dbase + 3];

    const float e0 = t0 - mu.x;
    const float e1 = t1 - mu.y;
    const float e2 = t2 - mu.z;
    const float e3 = t3 - mu.w;

    float q  = e0 * e0 * __frcp_rn(vv.x);
    q       += e1 * e1 * __frcp_rn(vv.y);
    q       += e2 * e2 * __frcp_rn(vv.z);
    q       += e3 * e3 * __frcp_rn(vv.w);

    // product of this thread's 4 variances (each in [0.5, 1.5])
    float pv = vv.x * vv.y * vv.z * vv.w;

    // Butterfly reduce across the 16 lanes of each gaussian.
    // xor offsets 1,2,4,8 never cross an aligned 16-lane boundary.
    #pragma unroll
    for (int off = 1; off < 16; off <<= 1) {
        q  += __shfl_xor_sync(0xffffffffu, q,  off);
        pv *= __shfl_xor_sync(0xffffffffu, pv, off);
    }

    if ((tid & 15) == 0) {
        const int g      = tid >> 4;
        const float logdet = __logf(pv);                     // == sum(log var)
        float lp = -0.5f * (D_LOG_2PI + logdet + q);
        lp = fminf(fmaxf(lp, -100.0f), 0.0f);
        lp += __logf(weights[(size_t)b * NG + g]);
        s_lp[g] = lp;
    }
    __syncthreads();

    // logsumexp over 16 gaussians, done by lanes 0..15 of warp 0
    if (tid < 16) {
        float v = s_lp[tid];
        float m = v;
        #pragma unroll
        for (int off = 8; off > 0; off >>= 1)
            m = fmaxf(m, __shfl_xor_sync(0x0000ffffu, m, off, 16));
        float e = __expf(v - m);
        #pragma unroll
        for (int off = 8; off > 0; off >>= 1)
            e += __shfl_xor_sync(0x0000ffffu, e, off, 16);
        if (tid == 0)
            out[b] = -(m + __logf(e));
    }
}

extern "C" void kernel_launch(void* const* d_in, const int* in_sizes, int n_in,
                              void* d_out, int out_size)
{
    const float* means   = (const float*)d_in[0];
    const float* covs    = (const float*)d_in[1];
    const float* weights = (const float*)d_in[2];
    const float* targets = (const float*)d_in[3];
    float*       out     = (float*)d_out;

    const int B = in_sizes[2] / NG;   // weights has B*16 elements

    gmm_loss_kernel<<<B, TPB>>>(means, covs, weights, targets, out);
}

// round 4
// speedup vs baseline: 1.0089x; 1.0089x over previous
#include <cuda_runtime.h>

#define NG    16
#define DD    64
#define WARPS 8
#define TPB   (WARPS * 32)

// 64 * log(2*pi)
#define D_LOG_2PI 117.6241322f

__global__ void __launch_bounds__(TPB) gmm_loss_kernel(
    const float4* __restrict__ means,
    const float4* __restrict__ covs,
    const float*  __restrict__ weights,
    const float4* __restrict__ targets,
    float* __restrict__ out)
{
    const int warp = threadIdx.x >> 5;
    const int lane = threadIdx.x & 31;
    const int b    = blockIdx.x * WARPS + warp;

    // Row base in units of float4: each row is 16*64 floats = 256 float4s.
    const size_t row4 = (size_t)b * 256;

    // Target float4 for this lane: element d = (lane*4) % 64, same for every chunk.
    const float4 t4 = targets[(size_t)b * 16 + (lane & 15)];

    // Stage all 16 float4 loads (8 chunks x {means, covs}) for max MLP.
    float4 mu[8], vv[8];
    #pragma unroll
    for (int c = 0; c < 8; c++) {
        const size_t idx = row4 + c * 32 + lane;
        mu[c] = means[idx];
        vv[c] = covs[idx];
    }

    // Per-chunk partial quad sums and variance products.
    // Chunk c, lanes 0-15 -> gaussian 2c; lanes 16-31 -> gaussian 2c+1.
    float q[8], pv[8];
    #pragma unroll
    for (int c = 0; c < 8; c++) {
        const float e0 = t4.x - mu[c].x;
        const float e1 = t4.y - mu[c].y;
        const float e2 = t4.z - mu[c].z;
        const float e3 = t4.w - mu[c].w;
        float s  = e0 * e0 * __frcp_rn(vv[c].x);
        s       += e1 * e1 * __frcp_rn(vv[c].y);
        s       += e2 * e2 * __frcp_rn(vv[c].z);
        s       += e3 * e3 * __frcp_rn(vv[c].w);
        q[c]  = s;
        pv[c] = vv[c].x * vv[c].y * vv[c].z * vv[c].w;
    }

    // Butterfly reduce within each 16-lane half (offsets 1,2,4,8 never cross halves).
    // Afterwards every lane in the half holds the full per-gaussian sum/product.
    #pragma unroll
    for (int c = 0; c < 8; c++) {
        #pragma unroll
        for (int off = 1; off < 16; off <<= 1) {
            q[c]  += __shfl_xor_sync(0xffffffffu, q[c],  off);
            pv[c] *= __shfl_xor_sync(0xffffffffu, pv[c], off);
        }
    }

    // Epilogue: 16 lanes each finish one gaussian in parallel.
    // lane l (l&15 < 8): chunk c = l&15, gaussian g = 2c + (l>=16).
    const int cidx = lane & 15;
    const int half = lane >> 4;
    float lp = -1e30f;
    if (cidx < 8) {
        const int g = 2 * cidx + half;
        const float logdet = __logf(pv[cidx]);   // == sum(log var)
        float v = -0.5f * (D_LOG_2PI + logdet + q[cidx]);
        v = fminf(fmaxf(v, -100.0f), 0.0f);
        v += __logf(weights[(size_t)b * NG + g]);
        lp = v;
    }

    // logsumexp over the 16 active lanes {0..7, 16..23} via xor offsets 16,1,2,4.
    float m = lp;
    m = fmaxf(m, __shfl_xor_sync(0xffffffffu, m, 16));
    m = fmaxf(m, __shfl_xor_sync(0xffffffffu, m, 1));
    m = fmaxf(m, __shfl_xor_sync(0xffffffffu, m, 2));
    m = fmaxf(m, __shfl_xor_sync(0xffffffffu, m, 4));

    float e = __expf(lp - m);   // inactive lanes underflow to 0
    e += __shfl_xor_sync(0xffffffffu, e, 16);
    e += __shfl_xor_sync(0xffffffffu, e, 1);
    e += __shfl_xor_sync(0xffffffffu, e, 2);
    e += __shfl_xor_sync(0xffffffffu, e, 4);

    if (lane == 0)
        out[b] = -(m + __logf(e));
}

extern "C" void kernel_launch(void* const* d_in, const int* in_sizes, int n_in,
                              void* d_out, int out_size)
{
    const float4* means   = (const float4*)d_in[0];
    const float4* covs    = (const float4*)d_in[1];
    const float*  weights = (const float*)d_in[2];
    const float4* targets = (const float4*)d_in[3];
    float*        out     = (float*)d_out;

    const int B = in_sizes[2] / NG;   // weights has B*16 elements

    gmm_loss_kernel<<<B / WARPS, TPB>>>(means, covs, weights, targets, out);
}

// round 7
// speedup vs baseline: 1.2832x; 1.2718x over previous
#include <cuda_runtime.h>

#define NG    16
#define WARPS 8
#define TPB   (WARPS * 32)

// 64 * log(2*pi)
#define D_LOG_2PI 117.6241322f

__global__ void __launch_bounds__(TPB) gmm_loss_kernel(
    const float4* __restrict__ means,
    const float4* __restrict__ covs,
    const float*  __restrict__ weights,
    const float4* __restrict__ targets,
    float* __restrict__ out)
{
    const int warp = threadIdx.x >> 5;
    const int lane = threadIdx.x & 31;
    const int b    = blockIdx.x * WARPS + warp;

    const int s    = lane & 15;   // sub-lane within 16-lane half
    const int half = lane >> 4;   // 0: even gaussians, 1: odd gaussians

    // Row base in units of float4: each row is 16*64 floats = 256 float4s.
    const size_t row4 = (size_t)b * 256;

    // Target float4 for this lane: element d = (lane*4) % 64, same for every chunk.
    const float4 t4 = targets[(size_t)b * 16 + s];

    // Stage all 16 float4 loads (8 chunks x {means, covs}) for max MLP.
    float4 mu[8], vv[8];
    #pragma unroll
    for (int c = 0; c < 8; c++) {
        const size_t idx = row4 + c * 32 + lane;
        mu[c] = means[idx];
        vv[c] = covs[idx];
    }

    // This lane's final gaussian after folding: value v = 4*b1 + 2*b2 + b3.
    const int vidx = ((s >> 1) & 1) * 4 + ((s >> 2) & 1) * 2 + ((s >> 3) & 1);
    const int g    = 2 * vidx + half;
    const float wt = __ldg(weights + (size_t)b * NG + g);  // overlap with folding

    // Per-chunk partial quad sums and variance products.
    // Chunk c, lanes 0-15 -> gaussian 2c; lanes 16-31 -> gaussian 2c+1.
    float q[8], pv[8];
    #pragma unroll
    for (int c = 0; c < 8; c++) {
        const float e0 = t4.x - mu[c].x;
        const float e1 = t4.y - mu[c].y;
        const float e2 = t4.z - mu[c].z;
        const float e3 = t4.w - mu[c].w;
        float sq = e0 * e0 * __frcp_rn(vv[c].x);
        sq      += e1 * e1 * __frcp_rn(vv[c].y);
        sq      += e2 * e2 * __frcp_rn(vv[c].z);
        sq      += e3 * e3 * __frcp_rn(vv[c].w);
        q[c]  = sq;
        pv[c] = vv[c].x * vv[c].y * vv[c].z * vv[c].w;
    }

    // ---- Value-lane folding: reduce 8 values over 16 lanes in 8 shuffles each ----
    const bool b3 = (s & 8) != 0;
    const bool b2 = (s & 4) != 0;
    const bool b1 = (s & 2) != 0;

    // Stage A (off=8): 8 -> 4 values. value(a_k) = 2k + b3
    float aq[4], ap[4];
    #pragma unroll
    for (int k = 0; k < 4; k++) {
        float kq = b3 ? q[2*k+1]  : q[2*k];
        float sq = b3 ? q[2*k]    : q[2*k+1];
        aq[k] = kq + __shfl_xor_sync(0xffffffffu, sq, 8);
        float kp = b3 ? pv[2*k+1] : pv[2*k];
        float sp = b3 ? pv[2*k]   : pv[2*k+1];
        ap[k] = kp * __shfl_xor_sync(0xffffffffu, sp, 8);
    }

    // Stage B (off=4): 4 -> 2. value(u_j) = 4j + 2*b2 + b3
    float uq[2], up[2];
    #pragma unroll
    for (int j = 0; j < 2; j++) {
        float kq = b2 ? aq[2*j+1] : aq[2*j];
        float sq = b2 ? aq[2*j]   : aq[2*j+1];
        uq[j] = kq + __shfl_xor_sync(0xffffffffu, sq, 4);
        float kp = b2 ? ap[2*j+1] : ap[2*j];
        float sp = b2 ? ap[2*j]   : ap[2*j+1];
        up[j] = kp * __shfl_xor_sync(0xffffffffu, sp, 4);
    }

    // Stage C (off=2): 2 -> 1. value = 4*b1 + 2*b2 + b3 = vidx
    float kq = b1 ? uq[1] : uq[0];
    float sq = b1 ? uq[0] : uq[1];
    float wq = kq + __shfl_xor_sync(0xffffffffu, sq, 2);
    float kp = b1 ? up[1] : up[0];
    float sp = b1 ? up[0] : up[1];
    float wp = kp * __shfl_xor_sync(0xffffffffu, sp, 2);

    // Stage D (off=1): complete the 16-lane sum (lanes s and s^1 now duplicate).
    wq += __shfl_xor_sync(0xffffffffu, wq, 1);
    wp *= __shfl_xor_sync(0xffffffffu, wp, 1);

    // ---- Epilogue: all 32 lanes finish their gaussian in parallel ----
    const float logdet = __logf(wp);                 // == sum(log var)
    float lp = -0.5f * (D_LOG_2PI + logdet + wq);
    lp = fminf(fmaxf(lp, -100.0f), 0.0f);
    lp += __logf(wt);

    // logsumexp over offsets {2,4,8,16}: bit0 is the duplicate axis, so each
    // of the 16 gaussians is counted exactly once.
    float m = lp;
    m = fmaxf(m, __shfl_xor_sync(0xffffffffu, m, 2));
    m = fmaxf(m, __shfl_xor_sync(0xffffffffu, m, 4));
    m = fmaxf(m, __shfl_xor_sync(0xffffffffu, m, 8));
    m = fmaxf(m, __shfl_xor_sync(0xffffffffu, m, 16));

    float e = __expf(lp - m);
    e += __shfl_xor_sync(0xffffffffu, e, 2);
    e += __shfl_xor_sync(0xffffffffu, e, 4);
    e += __shfl_xor_sync(0xffffffffu, e, 8);
    e += __shfl_xor_sync(0xffffffffu, e, 16);

    if (lane == 0)
        out[b] = -(m + __logf(e));
}

extern "C" void kernel_launch(void* const* d_in, const int* in_sizes, int n_in,
                              void* d_out, int out_size)
{
    const float4* means   = (const float4*)d_in[0];
    const float4* covs    = (const float4*)d_in[1];
    const float*  weights = (const float*)d_in[2];
    const float4* targets = (const float4*)d_in[3];
    float*        out     = (float*)d_out;

    const int B = in_sizes[2] / NG;   // weights has B*16 elements

    gmm_loss_kernel<<<B / WARPS, TPB>>>(means, covs, weights, targets, out);
}